// round 12
// baseline (speedup 1.0000x reference)
#include <cuda_runtime.h>
#include <cuda_bf16.h>
#include <math.h>

#define BB 8
#define NN 96
#define DD 16
#define H0 50
#define H1 50
#define OUTD 64
#define SLOPE 0.05f
#define CH 24

// Scratch (__device__ globals; allocation-free)
__device__ float g_A[BB*NN*H0];
__device__ float g_P[BB*NN*H0];
__device__ float g_deg[BB*NN];
__device__ float g_base[BB*NN*H1];
__device__ float g_xw3[BB*NN*OUTD];

__device__ __forceinline__ float leaky(float v) { return v >= 0.f ? v : SLOPE * v; }

// ---------------------------------------------------------------------------
// Kernel 1: per-(b,j) precompute (unchanged — proven at ~4.5us).
// ---------------------------------------------------------------------------
__global__ void __launch_bounds__(128) sgc_k1(
    const float* __restrict__ x, const float* __restrict__ adj,
    const float* __restrict__ W1, const float* __restrict__ b1,
    const float* __restrict__ W2, const float* __restrict__ b2,
    const float* __restrict__ W3, const float* __restrict__ b3)
{
    const int bj = blockIdx.x;
    const int b = bj / NN, j = bj % NN;
    const int tid = threadIdx.x;

    __shared__ float xb[NN*17];
    __shared__ float W1s[51*H0];
    __shared__ float W2s[33*H1];
    __shared__ float W3s[DD*OUTD];
    __shared__ float b1s[H0], b2s[H1], b3s[OUTD];
    __shared__ float adjrow[NN];
    __shared__ float disrow[NN];
    __shared__ float s[DD];
    __shared__ float red[2];

    {
        const float4* xB4 = (const float4*)(x + b*NN*DD);
        #pragma unroll
        for (int idx = tid; idx < NN*DD/4; idx += 128) {
            float4 v = xB4[idx];
            const int base = (idx >> 2)*17 + (idx & 3)*4;
            xb[base+0] = v.x; xb[base+1] = v.y; xb[base+2] = v.z; xb[base+3] = v.w;
        }
        const float2* W1v = (const float2*)W1;
        #pragma unroll
        for (int idx = tid; idx < 51*H0/2; idx += 128) ((float2*)W1s)[idx] = W1v[idx];
        const float2* W2v = (const float2*)W2;
        #pragma unroll
        for (int idx = tid; idx < 33*H1/2; idx += 128) ((float2*)W2s)[idx] = W2v[idx];
        const float4* W3v = (const float4*)W3;
        #pragma unroll
        for (int idx = tid; idx < DD*OUTD/4; idx += 128) ((float4*)W3s)[idx] = W3v[idx];
        if (tid < NN)   adjrow[tid] = adj[(b*NN + j)*NN + tid];
        if (tid < H0)   b1s[tid] = b1[tid];
        if (tid < H1)   b2s[tid] = b2[tid];
        if (tid < OUTD) b3s[tid] = b3[tid];
    }
    __syncthreads();

    if (tid < NN) {
        float d2 = 1e-10f;
        #pragma unroll
        for (int d = 0; d < DD; d++) {
            const float df = xb[j*17 + d] - xb[tid*17 + d];
            d2 += df * df;
        }
        disrow[tid] = sqrtf(d2);
    }
    __syncthreads();

    if (tid < 32) {
        float dg = 0.f, sd = 0.f;
        #pragma unroll
        for (int k = tid; k < NN; k += 32) {
            const float a = adjrow[k];
            dg += a; sd += a * disrow[k];
        }
        #pragma unroll
        for (int o = 16; o; o >>= 1) {
            dg += __shfl_down_sync(0xffffffffu, dg, o);
            sd += __shfl_down_sync(0xffffffffu, sd, o);
        }
        if (tid == 0) { red[0] = dg; red[1] = sd; g_deg[bj] = dg; }
    }
    if (tid >= 32 && tid < 32 + DD) {
        const int d = tid - 32;
        float acc = 0.f;
        #pragma unroll 4
        for (int k = 0; k < NN; k++) acc += adjrow[k] * xb[k*17 + d];
        s[d] = acc;
    }
    if (tid >= 64) {
        const int o = tid - 64;
        float acc = b3s[o];
        #pragma unroll
        for (int d = 0; d < DD; d++) acc += xb[j*17 + d] * W3s[d*OUTD + o];
        g_xw3[bj*OUTD + o] = acc;
    }
    __syncthreads();

    if (tid < H0) {
        const int h = tid;
        float Av = 0.f, Bv = 0.f, Cv = 0.f;
        #pragma unroll
        for (int d = 0; d < DD; d++) {
            const float xv = xb[j*17 + d];
            Av += xv   * W1s[d*H0 + h];
            Bv += xv   * W1s[(DD + d)*H0 + h];
            Cv += s[d] * W1s[(2*DD + d)*H0 + h];
        }
        g_A[bj*H0 + h] = Av;
        g_P[bj*H0 + h] = red[0]*(Bv + b1s[h]) + Cv + red[1] * W1s[(3*DD + 1)*H0 + h];
    } else if (tid >= 64 && tid < 64 + H1) {
        const int h1 = tid - 64;
        const float dg = red[0];
        float acc = dg * b2s[h1];
        #pragma unroll
        for (int d = 0; d < DD; d++) {
            acc += dg * xb[j*17 + d] * W2s[d*H1 + h1];
            acc += s[d]              * W2s[(DD + d)*H1 + h1];
        }
        acc += red[1] * W2s[(2*DD)*H1 + h1];
        g_base[bj*H1 + h1] = acc;
    }
}

// ---------------------------------------------------------------------------
// Kernel 2: TWO i's per block. 384 blocks, 256 threads.
// ---------------------------------------------------------------------------
__global__ void __launch_bounds__(256) sgc_k2(
    const float* __restrict__ x, const float* __restrict__ adj,
    const float* __restrict__ W1,
    const float* __restrict__ W2,
    const float* __restrict__ W3,
    float* __restrict__ out)
{
    const int b  = blockIdx.x / (NN/2);
    const int i0 = (blockIdx.x % (NN/2)) * 2;
    const int tid = threadIdx.x;
    const int w = tid >> 5, lane = tid & 31;

    __shared__ __align__(16) float xb[NN*17];
    __shared__ __align__(16) float W3s[H1*OUTD];     // W3 rows 16..65
    __shared__ __align__(8)  float W2s[H0*H1];       // W2 rows 33..82
    __shared__ __align__(8)  float Pst[2*CH*H0];
    __shared__ float disI[2*NN];
    __shared__ float sdik[2*CH], ddeg[2*CH], ddij[2*CH];
    __shared__ float taccS[2*H0], m2s[2*H1];
    __shared__ int   wcnt[6], nnzA[2];
    __shared__ unsigned char nzI[2*NN];

    // ---- Front epoch: all address-independent loads ----
    float Ah = 0.f, wij = 0.f, wik = 0.f, base2 = 0.f, xw3v = 0.f;
    {
        const float4* xv = (const float4*)(x + b*NN*DD);
        #pragma unroll
        for (int idx = tid; idx < NN*DD/4; idx += 256) {
            float4 v = xv[idx];
            const int base = (idx >> 2)*17 + (idx & 3)*4;
            xb[base] = v.x; xb[base+1] = v.y; xb[base+2] = v.z; xb[base+3] = v.w;
        }
        const float4* w3v = (const float4*)(W3 + DD*OUTD);
        #pragma unroll
        for (int idx = tid; idx < H1*OUTD/4; idx += 256) ((float4*)W3s)[idx] = w3v[idx];
        const float2* w2v = (const float2*)(W2 + (2*DD + 1)*H1);
        #pragma unroll
        for (int idx = tid; idx < H0*H1/2; idx += 256) ((float2*)W2s)[idx] = w2v[idx];
        if (tid < 2*H0) {
            const int ii = tid / H0, h = tid % H0;
            const int bi = (b*NN + i0 + ii);
            Ah    = g_A[bi*H0 + h];
            base2 = g_base[bi*H1 + h];
            wij   = W1[(3*DD + 0)*H0 + h];
            wik   = W1[(3*DD + 2)*H0 + h];
        } else if (tid >= 128) {
            const int idx = tid - 128, ii = idx >> 6, o = idx & 63;
            xw3v = g_xw3[(b*NN + i0 + ii)*OUTD + o];
        }
    }
    float adjv = 0.f;
    if (tid < 2*NN) adjv = adj[(b*NN + i0 + tid/NN)*NN + (tid % NN)];
    __syncthreads();

    // ---- dis rows (both i's) + compaction ----
    bool nzb = false; unsigned mk = 0u;
    int iiq = 0, kk = 0;
    if (tid < 2*NN) {              // warps 0..5 exactly; 96 = warp boundary
        iiq = tid / NN; kk = tid % NN;
        const int i = i0 + iiq;
        float d2 = 1e-10f;
        #pragma unroll
        for (int d = 0; d < DD; d++) {
            const float df = xb[i*17 + d] - xb[kk*17 + d];
            d2 += df * df;
        }
        disI[iiq*NN + kk] = sqrtf(d2);
        nzb = (adjv != 0.f);
        mk = __ballot_sync(~0u, nzb);
        if (lane == 0) wcnt[w] = __popc(mk);
    }
    __syncthreads();
    if (tid < 2*NN && nzb) {
        const int seg = w - iiq*3;
        int off = __popc(mk & ((1u << lane) - 1u));
        #pragma unroll
        for (int u = 0; u < 3; u++) if (u < seg) off += wcnt[iiq*3 + u];
        nzI[iiq*NN + off] = (unsigned char)kk;
    }
    if (tid < 2) nnzA[tid] = wcnt[tid*3] + wcnt[tid*3+1] + wcnt[tid*3+2];
    __syncthreads();

    const int nnz0 = nnzA[0], nnz1 = nnzA[1];
    const int mx = max(nnz0, nnz1);

    // ---- Chunked merged dependent epoch + t accumulation ----
    float accD = 0.f;
    const int slot = tid >> 2, sub = tid & 3;   // 4 threads per row, 48 slots (tid<192)
    for (int c0 = 0; c0 < mx; c0 += CH) {
        // (a) adj rows of neighbors: 4 threads/row × 6 float4
        float v = 0.f;
        bool act = false; int s_ii = 0, s_m = 0;
        if (tid < 192) {
            s_ii = slot / CH; s_m = slot % CH;
            act = (c0 + s_m) < (s_ii ? nnz1 : nnz0);
            if (act) {
                const int j = nzI[s_ii*NN + c0 + s_m];
                const float4* row4 = (const float4*)(adj + (b*NN + j)*NN) + sub*6;
                const float* dis = disI + s_ii*NN;
                #pragma unroll
                for (int q = 0; q < 6; q++) {
                    const float4 a = row4[q];
                    const int kb = sub*24 + q*4;
                    v += a.x*dis[kb] + a.y*dis[kb+1] + a.z*dis[kb+2] + a.w*dis[kb+3];
                }
            }
        }
        // (b) P rows (independent)
        for (int idx = tid; idx < 2*CH*(H0/2); idx += 256) {
            const int ii = idx / (CH*(H0/2));
            const int rem = idx % (CH*(H0/2));
            const int m = rem / (H0/2), q = rem % (H0/2);
            if (c0 + m < (ii ? nnz1 : nnz0)) {
                const int j = nzI[ii*NN + c0 + m];
                ((float2*)Pst)[(ii*CH + m)*(H0/2) + q] =
                    ((const float2*)(g_P + (b*NN + j)*H0))[q];
            }
        }
        // (c) deg (independent)
        if (tid < 2*CH) {
            const int ii = tid / CH, m = tid % CH;
            if (c0 + m < (ii ? nnz1 : nnz0)) {
                const int j = nzI[ii*NN + c0 + m];
                const float dg = g_deg[b*NN + j];
                ddeg[tid] = dg;
                ddij[tid] = dg * disI[ii*NN + j];
            }
        }
        // quad reduce -> sd_ik
        v += __shfl_xor_sync(~0u, v, 1);
        v += __shfl_xor_sync(~0u, v, 2);
        if (tid < 192 && sub == 0 && act) sdik[s_ii*CH + s_m] = v;
        __syncthreads();

        if (tid < 2*H0) {
            const int ii = tid / H0;
            const int lim = min((ii ? nnz1 : nnz0) - c0, CH);
            #pragma unroll 4
            for (int m = 0; m < lim; m++) {
                const int pm = ii*CH + m;
                const float Sv = fmaf(ddeg[pm], Ah,
                                 fmaf(ddij[pm], wij,
                                 fmaf(sdik[pm], wik, Pst[pm*H0 + (tid % H0)])));
                accD += leaky(Sv);
            }
        }
        __syncthreads();
    }
    if (tid < 2*H0) taccS[tid] = accD;
    __syncthreads();

    // ---- E: m2 (smem) ----
    if (tid < 2*H1) {
        const int ii = tid / H1, h1 = tid % H1;
        float acc = base2;
        #pragma unroll 10
        for (int h = 0; h < H0; h++)
            acc = fmaf(taccS[ii*H0 + h], W2s[h*H1 + h1], acc);
        m2s[tid] = leaky(acc);
    }
    __syncthreads();

    // ---- F: out (smem) ----
    if (tid >= 128) {
        const int idx = tid - 128, ii = idx >> 6, o = idx & 63;
        float acc = xw3v;
        #pragma unroll 10
        for (int h = 0; h < H1; h++)
            acc = fmaf(m2s[ii*H1 + h], W3s[h*OUTD + o], acc);
        out[(b*NN + i0 + ii)*OUTD + o] = leaky(acc);
    }
}

extern "C" void kernel_launch(void* const* d_in, const int* in_sizes, int n_in,
                              void* d_out, int out_size)
{
    const float* x   = (const float*)d_in[0];
    const float* adj = (const float*)d_in[1];
    const float* W1  = (const float*)d_in[2];
    const float* b1  = (const float*)d_in[3];
    const float* W2  = (const float*)d_in[4];
    const float* b2  = (const float*)d_in[5];
    const float* W3  = (const float*)d_in[6];
    const float* b3  = (const float*)d_in[7];
    float* out = (float*)d_out;

    sgc_k1<<<BB*NN, 128>>>(x, adj, W1, b1, W2, b2, W3, b3);
    sgc_k2<<<BB*(NN/2), 256>>>(x, adj, W1, W2, W3, out);
}

// round 17
// speedup vs baseline: 1.0019x; 1.0019x over previous
#include <cuda_runtime.h>
#include <cuda_bf16.h>
#include <math.h>

#define BB 8
#define NN 96
#define DD 16
#define H0 50
#define H1 50
#define OUTD 64
#define SLOPE 0.05f
#define CH 24

// Cross-block scratch (only P and deg cross blocks now)
__device__ float g_P[BB*NN*H0];
__device__ float g_deg[BB*NN];

__device__ __forceinline__ float leaky(float v) { return v >= 0.f ? v : SLOPE * v; }

// ---------------------------------------------------------------------------
// Kernel 1: minimal — P[j,:] and deg[j] only. 2 j's per block, 384 x 256.
// ---------------------------------------------------------------------------
__global__ void __launch_bounds__(256) sgc_k1(
    const float* __restrict__ x, const float* __restrict__ adj,
    const float* __restrict__ W1, const float* __restrict__ b1)
{
    const int b  = blockIdx.x / (NN/2);
    const int j0 = (blockIdx.x % (NN/2)) * 2;
    const int tid = threadIdx.x;
    const int w = tid >> 5, lane = tid & 31;

    __shared__ __align__(16) float xb[NN*17];
    __shared__ __align__(8)  float W1p[35*H0];   // W1 rows 16..50
    __shared__ float b1s[H0];
    __shared__ float adjR[2*NN];
    __shared__ float disR[2*NN];
    __shared__ float adjxS[2*DD];
    __shared__ float part[6], pdeg[6];
    __shared__ float degS[2], sdjkS[2];

    // P1: front epoch
    {
        const float4* xv = (const float4*)(x + b*NN*DD);
        #pragma unroll
        for (int idx = tid; idx < NN*DD/4; idx += 256) {
            float4 v = xv[idx];
            const int base = (idx >> 2)*17 + (idx & 3)*4;
            xb[base] = v.x; xb[base+1] = v.y; xb[base+2] = v.z; xb[base+3] = v.w;
        }
        const float2* w1v = (const float2*)(W1 + 16*H0);   // offset 800 floats, 8B aligned
        #pragma unroll
        for (int idx = tid; idx < 35*H0/2; idx += 256) ((float2*)W1p)[idx] = w1v[idx];
        if (tid < H0) b1s[tid] = b1[tid];
        if (tid < 2*NN) adjR[tid] = adj[(b*NN + j0 + tid/NN)*NN + (tid % NN)];
    }
    __syncthreads();

    // P2: dis rows (warps 0..5); adjx dense (warps 6..7)
    if (tid < 2*NN) {
        const int ii = tid / NN, k = tid % NN;
        const int j = j0 + ii;
        float d2 = 1e-10f;
        #pragma unroll
        for (int d = 0; d < DD; d++) {
            const float df = xb[j*17 + d] - xb[k*17 + d];
            d2 += df * df;
        }
        disR[ii*NN + k] = sqrtf(d2);
    } else {
        const int idx = tid - 192;     // 0..63, need 32
        if (idx < 2*DD) {
            const int ii = idx / DD, d = idx % DD;
            float acc = 0.f;
            #pragma unroll 4
            for (int k = 0; k < NN; k++) acc += adjR[ii*NN + k] * xb[k*17 + d];
            adjxS[idx] = acc;
        }
    }
    __syncthreads();

    // P3: deg/sdjk partials per warp segment
    if (tid < 2*NN) {
        const int ii = tid / NN;
        float a = adjR[tid];
        float dg = a, sd = a * disR[tid];
        #pragma unroll
        for (int o = 16; o; o >>= 1) {
            dg += __shfl_down_sync(~0u, dg, o);
            sd += __shfl_down_sync(~0u, sd, o);
        }
        if (lane == 0) { pdeg[w] = dg; part[w] = sd; }
        (void)ii;
    }
    __syncthreads();
    if (tid < 2) {
        degS[tid]  = pdeg[tid*3] + pdeg[tid*3+1] + pdeg[tid*3+2];
        sdjkS[tid] = part[tid*3] + part[tid*3+1] + part[tid*3+2];
        g_deg[b*NN + j0 + tid] = degS[tid];
    }
    __syncthreads();

    // P4: P rows (tid < 100)
    if (tid < 2*H0) {
        const int ii = tid / H0, h = tid % H0;
        const int j = j0 + ii;
        float Bv = 0.f, Cv = 0.f;
        #pragma unroll
        for (int d = 0; d < DD; d++) {
            Bv = fmaf(xb[j*17 + d],      W1p[d*H0 + h], Bv);          // W1 row 16+d
            Cv = fmaf(adjxS[ii*DD + d],  W1p[(DD + d)*H0 + h], Cv);   // W1 row 32+d
        }
        g_P[(b*NN + j)*H0 + h] =
            degS[ii]*(Bv + b1s[h]) + Cv + sdjkS[ii]*W1p[33*H0 + h];   // W1 row 49
    }
}

// ---------------------------------------------------------------------------
// Kernel 2: everything else, 2 i's per block. 384 x 256.
// ---------------------------------------------------------------------------
__global__ void __launch_bounds__(256) sgc_k2(
    const float* __restrict__ x, const float* __restrict__ adj,
    const float* __restrict__ W1, const float* __restrict__ b2v,
    const float* __restrict__ W2, const float* __restrict__ W3,
    const float* __restrict__ b3v,
    float* __restrict__ out)
{
    const int b  = blockIdx.x / (NN/2);
    const int i0 = (blockIdx.x % (NN/2)) * 2;
    const int tid = threadIdx.x;
    const int w = tid >> 5, lane = tid & 31;

    __shared__ __align__(16) float xb[NN*17];
    __shared__ __align__(16) float W3f[66*OUTD];    // all W3
    __shared__ __align__(8)  float W2f[83*H1];      // all W2
    __shared__ __align__(8)  float W1a[DD*H0];      // W1 rows 0..15
    __shared__ __align__(8)  float Pst[2*CH*H0];
    __shared__ float b2s[H1], b3s[OUTD];
    __shared__ float adjIs[2*NN];
    __shared__ float disI[2*NN];
    __shared__ float sdik[2*CH], ddeg[2*CH], ddij[2*CH];
    __shared__ float A_S[2*H0], taccS[2*H0], m2s[2*H1], base2S[2*H1], xw3S[2*OUTD];
    __shared__ float adjxS[2*DD], sdjkS[2];
    __shared__ int   wcnt[6], nnzA[2];
    __shared__ unsigned char nzI[2*NN];

    // ---- P1: front epoch (all independent) ----
    float wij = 0.f, wik = 0.f;
    {
        const float4* xv = (const float4*)(x + b*NN*DD);
        #pragma unroll
        for (int idx = tid; idx < NN*DD/4; idx += 256) {
            float4 v = xv[idx];
            const int base = (idx >> 2)*17 + (idx & 3)*4;
            xb[base] = v.x; xb[base+1] = v.y; xb[base+2] = v.z; xb[base+3] = v.w;
        }
        const float4* w3p = (const float4*)W3;
        #pragma unroll
        for (int idx = tid; idx < 66*OUTD/4; idx += 256) ((float4*)W3f)[idx] = w3p[idx];
        const float2* w2p = (const float2*)W2;
        #pragma unroll
        for (int idx = tid; idx < 83*H1/2; idx += 256) ((float2*)W2f)[idx] = w2p[idx];
        const float2* w1p = (const float2*)W1;
        #pragma unroll
        for (int idx = tid; idx < DD*H0/2; idx += 256) ((float2*)W1a)[idx] = w1p[idx];
        if (tid < 2*H0) {
            wij = W1[(3*DD + 0)*H0 + (tid % H0)];
            wik = W1[(3*DD + 2)*H0 + (tid % H0)];
        }
        if (tid < H1) b2s[tid] = b2v[tid];
        else if (tid < H1 + OUTD) b3s[tid - H1] = b3v[tid - H1];
        if (tid < 2*NN) adjIs[tid] = adj[(b*NN + i0 + tid/NN)*NN + (tid % NN)];
    }
    __syncthreads();

    // ---- P2: dis rows + compaction (warps 0..5) ----
    bool nzb = false; unsigned mk = 0u;
    int iiq = 0, kk = 0;
    if (tid < 2*NN) {
        iiq = tid / NN; kk = tid % NN;
        const int i = i0 + iiq;
        float d2 = 1e-10f;
        #pragma unroll
        for (int d = 0; d < DD; d++) {
            const float df = xb[i*17 + d] - xb[kk*17 + d];
            d2 += df * df;
        }
        disI[iiq*NN + kk] = sqrtf(d2);
        nzb = (adjIs[tid] != 0.f);
        mk = __ballot_sync(~0u, nzb);
        if (lane == 0) wcnt[w] = __popc(mk);
    } else {
        // warps 6..7: adjx dense (independent of dis/compaction)
        const int idx = tid - 192;
        if (idx < 2*DD) {
            const int ii = idx / DD, d = idx % DD;
            float acc = 0.f;
            #pragma unroll 4
            for (int k = 0; k < NN; k++) acc += adjIs[ii*NN + k] * xb[k*17 + d];
            adjxS[idx] = acc;
        }
    }
    __syncthreads();
    if (tid < 2*NN && nzb) {
        const int seg = w - iiq*3;
        int off = __popc(mk & ((1u << lane) - 1u));
        #pragma unroll
        for (int u = 0; u < 3; u++) if (u < seg) off += wcnt[iiq*3 + u];
        nzI[iiq*NN + off] = (unsigned char)kk;
    }
    if (tid < 2) nnzA[tid] = wcnt[tid*3] + wcnt[tid*3+1] + wcnt[tid*3+2];
    __syncthreads();

    const int nnz0 = nnzA[0], nnz1 = nnzA[1];
    const int mx = max(nnz0, nnz1);

    // ---- P3: A_i (w0..3), sdjk (w5), xw3 (w6..7) ----
    if (tid < 2*H0) {
        const int ii = tid / H0, h = tid % H0;
        const int i = i0 + ii;
        float acc = 0.f;
        #pragma unroll
        for (int d = 0; d < DD; d++) acc = fmaf(xb[i*17 + d], W1a[d*H0 + h], acc);
        A_S[tid] = acc;
    } else if (w == 5) {
        // lanes 0..15 -> ii=0, 16..31 -> ii=1; each lane sums 6 strided elems
        const int ii = lane >> 4, l = lane & 15;
        float acc = 0.f;
        #pragma unroll
        for (int q = 0; q < 6; q++) {
            const int k = l + q*16;
            acc += adjIs[ii*NN + k] * disI[ii*NN + k];
        }
        #pragma unroll
        for (int o = 8; o; o >>= 1) acc += __shfl_down_sync(~0u, acc, o);
        if (l == 0) sdjkS[ii] = acc;
    } else if (tid >= 192) {
        const int idx = tid - 192;        // 0..63, 2 outputs each
        #pragma unroll
        for (int q = 0; q < 2; q++) {
            const int oo = idx*2 + q, ii = oo >> 6, o = oo & 63;
            const int i = i0 + ii;
            float acc = b3s[o];
            #pragma unroll
            for (int d = 0; d < DD; d++) acc = fmaf(xb[i*17 + d], W3f[d*OUTD + o], acc);
            xw3S[oo] = acc;
        }
    }
    __syncthreads();

    // ---- P4: chunked merged dependent epoch + t accumulation ----
    float accD = 0.f;
    const int slot = tid >> 2, sub = tid & 3;
    for (int c0 = 0; c0 < mx; c0 += CH) {
        float v = 0.f;
        bool act = false; int s_ii = 0, s_m = 0;
        if (tid < 192) {
            s_ii = slot / CH; s_m = slot % CH;
            act = (c0 + s_m) < (s_ii ? nnz1 : nnz0);
            if (act) {
                const int j = nzI[s_ii*NN + c0 + s_m];
                const float4* row4 = (const float4*)(adj + (b*NN + j)*NN) + sub*6;
                const float* dis = disI + s_ii*NN;
                #pragma unroll
                for (int q = 0; q < 6; q++) {
                    const float4 a = row4[q];
                    const int kb = sub*24 + q*4;
                    v += a.x*dis[kb] + a.y*dis[kb+1] + a.z*dis[kb+2] + a.w*dis[kb+3];
                }
            }
        }
        for (int idx = tid; idx < 2*CH*(H0/2); idx += 256) {
            const int ii = idx / (CH*(H0/2));
            const int rem = idx % (CH*(H0/2));
            const int m = rem / (H0/2), q = rem % (H0/2);
            if (c0 + m < (ii ? nnz1 : nnz0)) {
                const int j = nzI[ii*NN + c0 + m];
                ((float2*)Pst)[(ii*CH + m)*(H0/2) + q] =
                    ((const float2*)(g_P + (b*NN + j)*H0))[q];
            }
        }
        if (tid < 2*CH) {
            const int ii = tid / CH, m = tid % CH;
            if (c0 + m < (ii ? nnz1 : nnz0)) {
                const int j = nzI[ii*NN + c0 + m];
                const float dg = g_deg[b*NN + j];
                ddeg[tid] = dg;
                ddij[tid] = dg * disI[ii*NN + j];
            }
        }
        v += __shfl_xor_sync(~0u, v, 1);
        v += __shfl_xor_sync(~0u, v, 2);
        if (tid < 192 && sub == 0 && act) sdik[s_ii*CH + s_m] = v;
        __syncthreads();

        if (tid < 2*H0) {
            const int ii = tid / H0;
            const float Ah = A_S[tid];
            const int lim = min((ii ? nnz1 : nnz0) - c0, CH);
            #pragma unroll 4
            for (int m = 0; m < lim; m++) {
                const int pm = ii*CH + m;
                const float Sv = fmaf(ddeg[pm], Ah,
                                 fmaf(ddij[pm], wij,
                                 fmaf(sdik[pm], wik, Pst[pm*H0 + (tid % H0)])));
                accD += leaky(Sv);
            }
        }
        __syncthreads();
    }

    // ---- P5: tacc write (t<100) || base2 (128<=t<228) ----
    if (tid < 2*H0) {
        taccS[tid] = accD;
    } else if (tid >= 128 && tid < 128 + 2*H1) {
        const int idx = tid - 128, ii = idx / H1, h1 = idx % H1;
        const int i = i0 + ii;
        const float dgi = (float)(ii ? nnz1 : nnz0);
        float acc = dgi * b2s[h1];
        #pragma unroll
        for (int d = 0; d < DD; d++) {
            acc = fmaf(dgi * xb[i*17 + d], W2f[d*H1 + h1], acc);
            acc = fmaf(adjxS[ii*DD + d],   W2f[(DD + d)*H1 + h1], acc);
        }
        acc = fmaf(sdjkS[ii], W2f[(2*DD)*H1 + h1], acc);
        base2S[idx] = acc;
    }
    __syncthreads();

    // ---- P6: m2 ----
    if (tid < 2*H1) {
        const int ii = tid / H1, h1 = tid % H1;
        float acc = base2S[tid];
        #pragma unroll 10
        for (int h = 0; h < H0; h++)
            acc = fmaf(taccS[ii*H0 + h], W2f[(2*DD + 1 + h)*H1 + h1], acc);
        m2s[tid] = leaky(acc);
    }
    __syncthreads();

    // ---- P7: out ----
    if (tid >= 128) {
        const int idx = tid - 128, ii = idx >> 6, o = idx & 63;
        float acc = xw3S[idx];
        #pragma unroll 10
        for (int h = 0; h < H1; h++)
            acc = fmaf(m2s[ii*H1 + h], W3f[(DD + h)*OUTD + o], acc);
        out[(b*NN + i0 + ii)*OUTD + o] = leaky(acc);
    }
}

extern "C" void kernel_launch(void* const* d_in, const int* in_sizes, int n_in,
                              void* d_out, int out_size)
{
    const float* x   = (const float*)d_in[0];
    const float* adj = (const float*)d_in[1];
    const float* W1  = (const float*)d_in[2];
    const float* b1  = (const float*)d_in[3];
    const float* W2  = (const float*)d_in[4];
    const float* b2  = (const float*)d_in[5];
    const float* W3  = (const float*)d_in[6];
    const float* b3  = (const float*)d_in[7];
    float* out = (float*)d_out;

    sgc_k1<<<BB*(NN/2), 256>>>(x, adj, W1, b1);
    sgc_k2<<<BB*(NN/2), 256>>>(x, adj, W1, b2, W2, W3, b3, out);
}